// round 2
// baseline (speedup 1.0000x reference)
#include <cuda_runtime.h>
#include <cstdint>

// ---------------------------------------------------------------------------
// Reference constants (fp32 round-trip exact).
// ---------------------------------------------------------------------------
__device__ constexpr float cH[16] = {
    -0.00443981f, 0.0244156f, -0.01410327f, 0.01784681f,
    -0.00239246f, 0.06331808f, 0.01457577f, 0.01753613f,
     0.01339214f, -0.0131252f, 0.02026613f, 0.00109124f,
    -0.01996419f, 0.00723148f, 0.03052537f, -0.00465259f};
__device__ constexpr float cD[16] = {
    -0.04305673f, 2.0701091e-05f, -0.028386816f, 0.065610707f,
     0.071529418f, -0.0010542608f, 0.0012044241f, 0.00077212957f,
    -0.00072495628f, 0.0010990113f, 0.00087419833f, -0.0031887756f,
    -0.019837018f, 0.00030188679f, 0.00022616754f, -0.0017746047f};
__device__ constexpr float cT[16] = {
    -0.1190194f, 0.03273299f, -0.05586114f, 0.07758415f,
    -0.06072911f, 0.04350465f, -0.06501344f, -0.07967568f,
    -0.08437239f, -0.07040057f, -0.07470815f, 0.01298669f,
     0.12695177f, 0.00617064f, -0.08909994f, 0.05016604f};

// All-fire output: fp32 chain of d[0..15] in the reference's accumulation
// order (out = 0 + d0 + d1 + ...). Valid for every |x| > max_t(C_t + T_t)
// = 0.24981 (+ <5e-7 float-chain slack). CUT = 0.26 gives 1e-2 margin.
__device__ constexpr float DSUM =
    (((((((((((((((-0.04305673f
      + 2.0701091e-05f) + -0.028386816f) + 0.065610707f) + 0.071529418f)
      + -0.0010542608f) + 0.0012044241f) + 0.00077212957f) + -0.00072495628f)
      + 0.0010990113f) + 0.00087419833f) + -0.0031887756f) + -0.019837018f)
      + 0.00030188679f) + 0.00022616754f) + -0.0017746047f);

constexpr float CUT = 0.26f;

// ---------------------------------------------------------------------------
// Exact per-element trajectory (identical to R0 kernel: rel_err == 0.0).
//  * (v-T)/(|v|+1) > 0  <=>  v > T   (denominator strictly positive)
//  * step 0 always fires (T[0] < 0 <= |x|)
// ---------------------------------------------------------------------------
__device__ __forceinline__ float snn_elem(float x) {
    float v = fabsf(x);
    float out = cD[0];
    v -= cH[1];
    bool z = v > cT[1];
    if (z) out += cD[1];
#pragma unroll
    for (int t = 2; t < 16; ++t) {
        if (z) v -= cH[t];
        z = v > cT[t];
        if (z) out += cD[t];
    }
    float r = (x > 0.0f) ? out : -out;
    return (x == 0.0f) ? 0.0f : r;
}

// ---------------------------------------------------------------------------
// Fast/slow split kernel with warp-local compaction.
//   - Each warp owns 512 contiguous elements (128 float4, slot-strided).
//   - Fast (|x| > CUT, ~79.5%): result = sign(x) XOR DSUM, one LOP3.
//   - Slow: ballot-compacted into a per-warp smem queue, drained at full
//     warp efficiency with the exact recurrence.
//   - Every output address written exactly once (no store races).
// ---------------------------------------------------------------------------
constexpr int WARPS_PER_BLOCK = 8;
constexpr int VEC_PER_WARP    = 128;   // 512 elements per warp
constexpr int QCAP            = 512;   // worst case: all slow

__global__ void __launch_bounds__(256) snn_fast_kernel(
    const float4* __restrict__ x4, float* __restrict__ out, int nvec) {
    __shared__ uint2 q[WARPS_PER_BLOCK][QCAP];

    const int warp = threadIdx.x >> 5;
    const int lane = threadIdx.x & 31;
    const unsigned ltmask = (1u << lane) - 1u;
    const int vbase = blockIdx.x * (WARPS_PER_BLOCK * VEC_PER_WARP)
                    + warp * VEC_PER_WARP;

    // Front-batched loads (MLP=4).
    float4 a[4];
    bool inb[4];
#pragma unroll
    for (int j = 0; j < 4; ++j) {
        int vi = vbase + j * 32 + lane;
        inb[j] = vi < nvec;
        a[j] = inb[j] ? x4[vi] : make_float4(1e9f, 1e9f, 1e9f, 1e9f);
    }

    unsigned qn = 0;   // warp-uniform queue count (no atomics needed)
#pragma unroll
    for (int j = 0; j < 4; ++j) {
        int vi = vbase + j * 32 + lane;
        const float xs[4] = {a[j].x, a[j].y, a[j].z, a[j].w};
#pragma unroll
        for (int c = 0; c < 4; ++c) {
            float xv = xs[c];
            bool fast = fabsf(xv) > CUT;
            bool slow = (!fast) && inb[j];
            unsigned m = __ballot_sync(0xffffffffu, slow);
            if (slow) {
                unsigned rank = __popc(m & ltmask);
                q[warp][qn + rank] =
                    make_uint2(__float_as_uint(xv), (unsigned)(vi * 4 + c));
            }
            if (fast && inb[j]) {
                // sign(x) applied by XOR: DSUM > 0, x != 0 here.
                unsigned rb = (__float_as_uint(xv) & 0x80000000u)
                            ^ __float_as_uint(DSUM);
                out[vi * 4 + c] = __uint_as_float(rb);
            }
            qn += __popc(m);
        }
    }

    __syncwarp();

    // Drain the slow queue at full warp efficiency (~3.4 iterations avg).
    for (unsigned i = lane; i < qn; i += 32) {
        uint2 e = q[warp][i];
        out[e.y] = snn_elem(__uint_as_float(e.x));
    }
}

__global__ void snn_tail_kernel(const float* __restrict__ x,
                                float* __restrict__ o, int base, int n) {
    int i = base + blockIdx.x * blockDim.x + threadIdx.x;
    if (i < n) o[i] = snn_elem(x[i]);
}

extern "C" void kernel_launch(void* const* d_in, const int* in_sizes, int n_in,
                              void* d_out, int out_size) {
    const float* x = (const float*)d_in[0];
    float* out = (float*)d_out;
    int n = in_sizes[0];

    int nvec = n >> 2;
    if (nvec > 0) {
        int vec_per_block = WARPS_PER_BLOCK * VEC_PER_WARP;  // 1024
        int blocks = (nvec + vec_per_block - 1) / vec_per_block;
        snn_fast_kernel<<<blocks, 256>>>((const float4*)x, out, nvec);
    }
    int rem = n & 3;
    if (rem > 0) {
        snn_tail_kernel<<<1, 32>>>(x, out, nvec << 2, n);
    }
}

// round 3
// speedup vs baseline: 1.2676x; 1.2676x over previous
#include <cuda_runtime.h>
#include <cstdint>

// ---------------------------------------------------------------------------
// Reference constants (fp32 round-trip exact).
// ---------------------------------------------------------------------------
__device__ constexpr float cH[16] = {
    -0.00443981f, 0.0244156f, -0.01410327f, 0.01784681f,
    -0.00239246f, 0.06331808f, 0.01457577f, 0.01753613f,
     0.01339214f, -0.0131252f, 0.02026613f, 0.00109124f,
    -0.01996419f, 0.00723148f, 0.03052537f, -0.00465259f};
__device__ constexpr float cD[16] = {
    -0.04305673f, 2.0701091e-05f, -0.028386816f, 0.065610707f,
     0.071529418f, -0.0010542608f, 0.0012044241f, 0.00077212957f,
    -0.00072495628f, 0.0010990113f, 0.00087419833f, -0.0031887756f,
    -0.019837018f, 0.00030188679f, 0.00022616754f, -0.0017746047f};
__device__ constexpr float cT[16] = {
    -0.1190194f, 0.03273299f, -0.05586114f, 0.07758415f,
    -0.06072911f, 0.04350465f, -0.06501344f, -0.07967568f,
    -0.08437239f, -0.07040057f, -0.07470815f, 0.01298669f,
     0.12695177f, 0.00617064f, -0.08909994f, 0.05016604f};

// All-fire output: fp32 chain of d[0..15] in the reference's accumulation
// order. Valid for every |x| > max_t(C_t + T_t) = 0.24981 (+ <5e-7 slack).
// CUT = 0.26 gives margin; empirically validated (R2 rel_err == 0.0).
__device__ constexpr float DSUM =
    (((((((((((((((-0.04305673f
      + 2.0701091e-05f) + -0.028386816f) + 0.065610707f) + 0.071529418f)
      + -0.0010542608f) + 0.0012044241f) + 0.00077212957f) + -0.00072495628f)
      + 0.0010990113f) + 0.00087419833f) + -0.0031887756f) + -0.019837018f)
      + 0.00030188679f) + 0.00022616754f) + -0.0017746047f);

constexpr float CUT = 0.26f;

// Exact per-element trajectory (identical to R0: rel_err == 0.0).
__device__ __forceinline__ float snn_elem(float x) {
    float v = fabsf(x);
    float out = cD[0];
    v -= cH[1];
    bool z = v > cT[1];
    if (z) out += cD[1];
#pragma unroll
    for (int t = 2; t < 16; ++t) {
        if (z) v -= cH[t];
        z = v > cT[t];
        if (z) out += cD[t];
    }
    float r = (x > 0.0f) ? out : -out;
    return (x == 0.0f) ? 0.0f : r;
}

// ---------------------------------------------------------------------------
// R3: branchless fast path with COALESCED float4 stores; slow elements
// (~20.6%) ballot-compacted into a per-warp smem queue and their addresses
// overwritten by the drain (same warp, __syncwarp memory-orders the stores;
// L2 merges the double-write — R2 showed zero DRAM amplification).
// ---------------------------------------------------------------------------
constexpr int WARPS_PER_BLOCK = 8;
constexpr int VEC_PER_WARP    = 128;   // 512 elements per warp
constexpr int QCAP            = 512;   // worst case: all slow

__global__ void __launch_bounds__(256) snn_kernel(
    const float4* __restrict__ x4, float4* __restrict__ o4, int nvec) {
    __shared__ uint2 q[WARPS_PER_BLOCK][QCAP];

    const int warp = threadIdx.x >> 5;
    const int lane = threadIdx.x & 31;
    const unsigned ltmask = (1u << lane) - 1u;
    const int vbase = blockIdx.x * (WARPS_PER_BLOCK * VEC_PER_WARP)
                    + warp * VEC_PER_WARP;
    float* out_s = (float*)o4;

    // Front-batched loads (MLP=4).
    float4 a[4];
    bool inb[4];
#pragma unroll
    for (int j = 0; j < 4; ++j) {
        int vi = vbase + j * 32 + lane;
        inb[j] = vi < nvec;
        a[j] = inb[j] ? x4[vi] : make_float4(1e9f, 1e9f, 1e9f, 1e9f);
    }

    const unsigned dsum_bits = __float_as_uint(DSUM);
    unsigned qn = 0;   // warp-uniform queue count
#pragma unroll
    for (int j = 0; j < 4; ++j) {
        int vi = vbase + j * 32 + lane;
        const float xs[4] = {a[j].x, a[j].y, a[j].z, a[j].w};
        float rs[4];
#pragma unroll
        for (int c = 0; c < 4; ++c) {
            unsigned xb = __float_as_uint(xs[c]);
            // Branchless all-fire result: sign(x) applied by XOR (DSUM > 0).
            rs[c] = __uint_as_float((xb & 0x80000000u) ^ dsum_bits);
            bool slow = (fabsf(xs[c]) < CUT) && inb[j];
            unsigned m = __ballot_sync(0xffffffffu, slow);
            if (slow) {
                q[warp][qn + __popc(m & ltmask)] =
                    make_uint2(xb, (unsigned)(vi * 4 + c));
            }
            qn += __popc(m);
        }
        // Coalesced store; slow components hold a placeholder, overwritten
        // below by the same warp after __syncwarp (memory-ordered).
        if (inb[j]) o4[vi] = make_float4(rs[0], rs[1], rs[2], rs[3]);
    }

    __syncwarp();

    // Drain: exact recurrence at full warp efficiency (~3.3 iterations).
    for (unsigned i = lane; i < qn; i += 32) {
        uint2 e = q[warp][i];
        out_s[e.y] = snn_elem(__uint_as_float(e.x));
    }
}

__global__ void snn_tail_kernel(const float* __restrict__ x,
                                float* __restrict__ o, int base, int n) {
    int i = base + blockIdx.x * blockDim.x + threadIdx.x;
    if (i < n) o[i] = snn_elem(x[i]);
}

extern "C" void kernel_launch(void* const* d_in, const int* in_sizes, int n_in,
                              void* d_out, int out_size) {
    const float* x = (const float*)d_in[0];
    float* out = (float*)d_out;
    int n = in_sizes[0];

    int nvec = n >> 2;
    if (nvec > 0) {
        int vec_per_block = WARPS_PER_BLOCK * VEC_PER_WARP;  // 1024
        int blocks = (nvec + vec_per_block - 1) / vec_per_block;
        snn_kernel<<<blocks, 256>>>((const float4*)x, (float4*)out, nvec);
    }
    int rem = n & 3;
    if (rem > 0) {
        snn_tail_kernel<<<1, 32>>>(x, out, nvec << 2, n);
    }
}

// round 4
// speedup vs baseline: 1.5878x; 1.2526x over previous
#include <cuda_runtime.h>
#include <cstdint>

// ---------------------------------------------------------------------------
// Reference constants (fp32 round-trip exact).
// ---------------------------------------------------------------------------
__device__ constexpr float cH[16] = {
    -0.00443981f, 0.0244156f, -0.01410327f, 0.01784681f,
    -0.00239246f, 0.06331808f, 0.01457577f, 0.01753613f,
     0.01339214f, -0.0131252f, 0.02026613f, 0.00109124f,
    -0.01996419f, 0.00723148f, 0.03052537f, -0.00465259f};
__device__ constexpr float cD[16] = {
    -0.04305673f, 2.0701091e-05f, -0.028386816f, 0.065610707f,
     0.071529418f, -0.0010542608f, 0.0012044241f, 0.00077212957f,
    -0.00072495628f, 0.0010990113f, 0.00087419833f, -0.0031887756f,
    -0.019837018f, 0.00030188679f, 0.00022616754f, -0.0017746047f};
__device__ constexpr float cT[16] = {
    -0.1190194f, 0.03273299f, -0.05586114f, 0.07758415f,
    -0.06072911f, 0.04350465f, -0.06501344f, -0.07967568f,
    -0.08437239f, -0.07040057f, -0.07470815f, 0.01298669f,
     0.12695177f, 0.00617064f, -0.08909994f, 0.05016604f};

// All-fire output (reference's fp32 accumulation order). Valid for
// |x| > 0.24981 + eps; CUT = 0.26 (validated rel_err==0 in R2/R3).
__device__ constexpr float DSUM =
    (((((((((((((((-0.04305673f
      + 2.0701091e-05f) + -0.028386816f) + 0.065610707f) + 0.071529418f)
      + -0.0010542608f) + 0.0012044241f) + 0.00077212957f) + -0.00072495628f)
      + 0.0010990113f) + 0.00087419833f) + -0.0031887756f) + -0.019837018f)
      + 0.00030188679f) + 0.00022616754f) + -0.0017746047f);

constexpr float CUT      = 0.26f;
constexpr int   NBUCKETS = 2048;
constexpr float KSCALE   = (float)NBUCKETS / CUT;      // compile-time fp32
constexpr unsigned SENTINEL = 0x7FFFFFFFu;             // canonical NaN flag

// Exact per-element trajectory (bit-identical to reference; rel_err==0 in R0).
__device__ __forceinline__ float snn_elem(float x) {
    float v = fabsf(x);
    float out = cD[0];                 // step 0 always fires (T[0] < 0 <= v)
    v -= cH[1];
    bool z = v > cT[1];                // (v-T)/(|v|+1) > 0  <=>  v > T
    if (z) out += cD[1];
#pragma unroll
    for (int t = 2; t < 16; ++t) {
        if (z) v -= cH[t];
        z = v > cT[t];
        if (z) out += cD[t];
    }
    float r = (x > 0.0f) ? out : -out;
    return (x == 0.0f) ? 0.0f : r;
}

// Recurrence on u = |x| >= 0, returning firing pattern + exact output.
__device__ __forceinline__ float snn_pattern(float u, unsigned& mask) {
    float v = u;
    float out = cD[0];
    mask = 1u;                         // step 0 fires
    v -= cH[1];
    bool z = v > cT[1];
    if (z) { out += cD[1]; mask |= 2u; }
#pragma unroll
    for (int t = 2; t < 16; ++t) {
        if (z) v -= cH[t];
        z = v > cT[t];
        if (z) { out += cD[t]; mask |= (1u << t); }
    }
    return out;
}

__device__ __forceinline__ float sub_ulps(float f, int k) {
    return __int_as_float(__float_as_int(f) - k);      // f > 0 assumed
}
__device__ __forceinline__ float add_ulps(float f, int k) {
    return __int_as_float(__float_as_int(f) + k);
}

// Table padded to 2052 for float4 copy. [0..2047] buckets, [2048] = DSUM.
__device__ float g_table[2052];

// ---------------------------------------------------------------------------
// Precompute: bucket i covers u with trunc(fl(u*KSCALE)) == i. Evaluate the
// exact recurrence at conservatively widened endpoints (+-8 ulp around the
// real boundaries i/KSCALE); fp32 monotonicity => equal firing patterns at
// both ends imply a constant pattern (and hence bit-exact constant output)
// across the whole bucket. Otherwise flag with SENTINEL -> exact fallback.
// ---------------------------------------------------------------------------
__global__ void build_table_kernel() {
    int i = blockIdx.x * blockDim.x + threadIdx.x;
    if (i >= 2052) return;
    if (i >= 2048) { g_table[i] = DSUM; return; }      // all-fire region
    if (i == 0)    { g_table[0] = __uint_as_float(SENTINEL); return; } // x==0
    double invK = 1.0 / (double)KSCALE;
    float lo = sub_ulps((float)( (double)i      * invK), 8);
    float hi = add_ulps((float)(((double)i + 1.0) * invK), 8);
    unsigned mlo, mhi;
    float out = snn_pattern(lo, mlo);
    snn_pattern(hi, mhi);
    g_table[i] = (mlo == mhi) ? out : __uint_as_float(SENTINEL);
}

// ---------------------------------------------------------------------------
// Main kernel: 16 elements/thread. Per element: FMUL(|x|*K), F2I, MIN, LDS,
// sign-XOR. Sentinel hits (breakpoint buckets, <~1%) recompute exactly and
// overwrite their own placeholder (same thread, program order).
// ---------------------------------------------------------------------------
constexpr int VEC_PER_BLOCK = 1024;    // 256 threads x 4 float4

__global__ void __launch_bounds__(256) snn_tbl_kernel(
    const float4* __restrict__ x4, float4* __restrict__ o4, int nvec) {
    __shared__ unsigned tbl[2052];

    // Cooperative table copy (float4).
    {
        const float4* src = (const float4*)g_table;
        float4* dst = (float4*)tbl;
#pragma unroll
        for (int k = 0; k < 3; ++k) {
            int t = threadIdx.x + k * 256;
            if (t < 513) dst[t] = src[t];
        }
    }
    __syncthreads();

    const int base = blockIdx.x * VEC_PER_BLOCK + threadIdx.x;
    float* out_s = (float*)o4;

    // Front-batched loads (MLP=4).
    float4 a[4];
    bool inb[4];
#pragma unroll
    for (int j = 0; j < 4; ++j) {
        int vi = base + j * 256;
        inb[j] = vi < nvec;
        a[j] = inb[j] ? x4[vi] : make_float4(1e9f, 1e9f, 1e9f, 1e9f);
    }

#pragma unroll
    for (int j = 0; j < 4; ++j) {
        int vi = base + j * 256;
        const float xs[4] = {a[j].x, a[j].y, a[j].z, a[j].w};
        unsigned fb[4], rb[4];
#pragma unroll
        for (int c = 0; c < 4; ++c) {
            float t = fabsf(xs[c]) * KSCALE;      // FMUL with |.| modifier
            int idx = min((int)t, NBUCKETS);      // F2I.TRUNC + IMNMX
            fb[c] = tbl[idx];                     // LDS (random, ~3.5-way)
            rb[c] = (__float_as_uint(xs[c]) & 0x80000000u) ^ fb[c];
        }
        if (inb[j]) {
            o4[vi] = make_float4(__uint_as_float(rb[0]), __uint_as_float(rb[1]),
                                 __uint_as_float(rb[2]), __uint_as_float(rb[3]));
            // Rare exact fallback; overwrites own placeholder (same thread).
#pragma unroll
            for (int c = 0; c < 4; ++c) {
                if (fb[c] == SENTINEL) out_s[vi * 4 + c] = snn_elem(xs[c]);
            }
        }
    }
}

__global__ void snn_tail_kernel(const float* __restrict__ x,
                                float* __restrict__ o, int base, int n) {
    int i = base + blockIdx.x * blockDim.x + threadIdx.x;
    if (i < n) o[i] = snn_elem(x[i]);
}

extern "C" void kernel_launch(void* const* d_in, const int* in_sizes, int n_in,
                              void* d_out, int out_size) {
    const float* x = (const float*)d_in[0];
    float* out = (float*)d_out;
    int n = in_sizes[0];

    build_table_kernel<<<9, 256>>>();          // 2304 threads >= 2052

    int nvec = n >> 2;
    if (nvec > 0) {
        int blocks = (nvec + VEC_PER_BLOCK - 1) / VEC_PER_BLOCK;
        snn_tbl_kernel<<<blocks, 256>>>((const float4*)x, (float4*)out, nvec);
    }
    int rem = n & 3;
    if (rem > 0) {
        snn_tail_kernel<<<1, 32>>>(x, out, nvec << 2, n);
    }
}